// round 1
// baseline (speedup 1.0000x reference)
#include <cuda_runtime.h>
#include <math.h>

#define N_TOK 4096
#define D_MODEL 320
#define HEADS 8
#define DH 40
#define SCALE 0.15811388300841897f  // 40^-0.5

// ---------------- scratch (no allocs allowed) ----------------
__device__ float g_Q[N_TOK * D_MODEL];
__device__ float g_K[N_TOK * D_MODEL];
__device__ float g_V[N_TOK * D_MODEL];
__device__ float g_A[N_TOK * D_MODEL];   // attention output (head-merged)
__device__ int   g_code[N_TOK];
__device__ float g_vmean[D_MODEL];

// ---------------- phase-code kernel ----------------
__global__ void code_kernel(const float* __restrict__ g, int* __restrict__ code) {
    int i = blockIdx.x * 256 + threadIdx.x;
    if (i < N_TOK) {
        int c = 0;
        if (g[i]            > 0.5f) c |= 1;
        if (g[N_TOK + i]    > 0.5f) c |= 2;
        if (g[2*N_TOK + i]  > 0.5f) c |= 4;
        code[i] = c;
    }
}

// ---------------- column mean of V (for fully-masked rows) ----------------
__global__ void vmean_kernel(const float* __restrict__ V, float* __restrict__ vm) {
    __shared__ float red[256];
    int c = blockIdx.x;
    float s = 0.f;
    for (int r = threadIdx.x; r < N_TOK; r += 256) s += V[r * D_MODEL + c];
    red[threadIdx.x] = s;
    __syncthreads();
    for (int o = 128; o > 0; o >>= 1) {
        if (threadIdx.x < o) red[threadIdx.x] += red[threadIdx.x + o];
        __syncthreads();
    }
    if (threadIdx.x == 0) vm[c] = red[0] * (1.f / (float)N_TOK);
}

// ---------------- generic tiled fp32 GEMM: C[MxN] = A[MxK]*B[KxN] (+bias) ----------------
__global__ __launch_bounds__(256) void gemm64(
    const float* __restrict__ A, const float* __restrict__ B,
    const float* __restrict__ bias, float* __restrict__ C,
    int M, int N, int K)
{
    __shared__ float As[16][68];
    __shared__ float Bs[16][68];
    int tid = threadIdx.x;
    int m0 = blockIdx.y * 64;
    int n0 = blockIdx.x * 64;
    int ty = tid >> 4, tx = tid & 15;

    int lr = tid >> 2;            // A-load row (0..63)
    int lk = (tid & 3) * 4;       // A-load k offset
    int bk = tid >> 4;            // B-load k (0..15)
    int bc = (tid & 15) * 4;      // B-load col offset

    float acc[4][4];
    #pragma unroll
    for (int i = 0; i < 4; ++i)
        #pragma unroll
        for (int j = 0; j < 4; ++j) acc[i][j] = 0.f;

    for (int k0 = 0; k0 < K; k0 += 16) {
        float4 av = *(const float4*)&A[(m0 + lr) * K + k0 + lk];
        As[lk + 0][lr] = av.x; As[lk + 1][lr] = av.y;
        As[lk + 2][lr] = av.z; As[lk + 3][lr] = av.w;
        float4 bv = *(const float4*)&B[(k0 + bk) * N + n0 + bc];
        *(float4*)&Bs[bk][bc] = bv;
        __syncthreads();
        #pragma unroll
        for (int kk = 0; kk < 16; ++kk) {
            float a[4], b[4];
            #pragma unroll
            for (int i = 0; i < 4; ++i) a[i] = As[kk][ty * 4 + i];
            #pragma unroll
            for (int j = 0; j < 4; ++j) b[j] = Bs[kk][tx * 4 + j];
            #pragma unroll
            for (int i = 0; i < 4; ++i)
                #pragma unroll
                for (int j = 0; j < 4; ++j)
                    acc[i][j] = fmaf(a[i], b[j], acc[i][j]);
        }
        __syncthreads();
    }
    #pragma unroll
    for (int i = 0; i < 4; ++i) {
        int row = m0 + ty * 4 + i;
        #pragma unroll
        for (int j = 0; j < 4; ++j) {
            int col = n0 + tx * 4 + j;
            float v = acc[i][j];
            if (bias) v += bias[col];
            C[row * N + col] = v;
        }
    }
}

// ---------------- masked flash attention ----------------
// grid (64 qtiles, 8 heads), 256 threads: 64 rows x 4 lanes/row.
// Each lane does independent online softmax over keys j = 4s+lane4 per tile,
// then shuffle-merges (m,l,O[40]) across the 4 lanes.
__global__ __launch_bounds__(256) void attn_kernel(
    const float* __restrict__ Q, const float* __restrict__ Km,
    const float* __restrict__ Vm, const int* __restrict__ code,
    const float* __restrict__ vmean, float* __restrict__ out)
{
    int h = blockIdx.y, qt = blockIdx.x;
    int tid = threadIdx.x;
    int grp = tid >> 2, lane4 = tid & 3;
    int row = qt * 64 + grp;
    int hoff = h * DH;
    int mycode = code[row];
    bool active = (mycode != 0);

    __shared__ float Ksm[64 * DH];
    __shared__ float Vsm[64 * DH];
    __shared__ int csm[64];

    float q[DH];
    if (active) {
        #pragma unroll
        for (int d4 = 0; d4 < 10; ++d4) {
            float4 t = *(const float4*)&Q[row * D_MODEL + hoff + d4 * 4];
            q[d4*4+0] = t.x; q[d4*4+1] = t.y; q[d4*4+2] = t.z; q[d4*4+3] = t.w;
        }
    } else {
        #pragma unroll
        for (int d = 0; d < DH; ++d) q[d] = 0.f;
    }

    float m = -1e30f, l = 0.f;
    float O[DH];
    #pragma unroll
    for (int d = 0; d < DH; ++d) O[d] = 0.f;

    for (int kt = 0; kt < 64; ++kt) {
        if (tid < 64) csm[tid] = code[kt * 64 + tid];
        for (int v = tid; v < 640; v += 256) {
            int r = v / 10, d4 = v - r * 10;
            int gi = (kt * 64 + r) * D_MODEL + hoff + d4 * 4;
            *(float4*)&Ksm[r * DH + d4 * 4] = *(const float4*)&Km[gi];
            *(float4*)&Vsm[r * DH + d4 * 4] = *(const float4*)&Vm[gi];
        }
        __syncthreads();
        if (active) {
            #pragma unroll 2
            for (int s = 0; s < 16; ++s) {
                int jj = (s << 2) | lane4;   // interleaved: conflict-free LDS.128
                if ((mycode & csm[jj]) == 0) continue;
                const float4* kp = (const float4*)(Ksm + jj * DH);
                float d0 = 0.f, d1 = 0.f;
                #pragma unroll
                for (int d4 = 0; d4 < 10; d4 += 2) {
                    float4 k0 = kp[d4], k1 = kp[d4 + 1];
                    d0 = fmaf(q[d4*4+0], k0.x, d0); d0 = fmaf(q[d4*4+1], k0.y, d0);
                    d0 = fmaf(q[d4*4+2], k0.z, d0); d0 = fmaf(q[d4*4+3], k0.w, d0);
                    d1 = fmaf(q[d4*4+4], k1.x, d1); d1 = fmaf(q[d4*4+5], k1.y, d1);
                    d1 = fmaf(q[d4*4+6], k1.z, d1); d1 = fmaf(q[d4*4+7], k1.w, d1);
                }
                float sc = (d0 + d1) * SCALE;
                const float4* vp = (const float4*)(Vsm + jj * DH);
                if (sc <= m) {
                    float p = __expf(sc - m);
                    l += p;
                    #pragma unroll
                    for (int d4 = 0; d4 < 10; ++d4) {
                        float4 vv = vp[d4];
                        O[d4*4+0] = fmaf(p, vv.x, O[d4*4+0]);
                        O[d4*4+1] = fmaf(p, vv.y, O[d4*4+1]);
                        O[d4*4+2] = fmaf(p, vv.z, O[d4*4+2]);
                        O[d4*4+3] = fmaf(p, vv.w, O[d4*4+3]);
                    }
                } else {
                    float f = __expf(m - sc);
                    m = sc;
                    l = fmaf(l, f, 1.f);
                    #pragma unroll
                    for (int d4 = 0; d4 < 10; ++d4) {
                        float4 vv = vp[d4];
                        O[d4*4+0] = fmaf(O[d4*4+0], f, vv.x);
                        O[d4*4+1] = fmaf(O[d4*4+1], f, vv.y);
                        O[d4*4+2] = fmaf(O[d4*4+2], f, vv.z);
                        O[d4*4+3] = fmaf(O[d4*4+3], f, vv.w);
                    }
                }
            }
        }
        __syncthreads();
    }

    // merge across the 4 lanes of this row (run unconditionally: shuffles need convergence)
    #pragma unroll
    for (int off = 1; off < 4; off <<= 1) {
        float mo = __shfl_xor_sync(0xffffffffu, m, off);
        float lo = __shfl_xor_sync(0xffffffffu, l, off);
        float mn = fmaxf(m, mo);
        float a = __expf(m - mn);
        float b = __expf(mo - mn);
        l = l * a + lo * b;
        #pragma unroll
        for (int d = 0; d < DH; ++d) {
            float od = __shfl_xor_sync(0xffffffffu, O[d], off);
            O[d] = O[d] * a + od * b;
        }
        m = mn;
    }

    if (active) {
        float inv = 1.f / l;
        #pragma unroll
        for (int d = 0; d < 10; ++d)
            out[row * D_MODEL + hoff + lane4 * 10 + d] = O[lane4 * 10 + d] * inv;
    } else {
        // fully-masked row: reference softmax over all -FLT_MAX is uniform -> mean of V
        #pragma unroll
        for (int d = 0; d < 10; ++d)
            out[row * D_MODEL + hoff + lane4 * 10 + d] = vmean[hoff + lane4 * 10 + d];
    }
}

extern "C" void kernel_launch(void* const* d_in, const int* in_sizes, int n_in,
                              void* d_out, int out_size) {
    const float* x     = (const float*)d_in[0];
    const float* gmask = (const float*)d_in[1];
    const float* Wq    = (const float*)d_in[2];
    const float* Wk    = (const float*)d_in[3];
    const float* Wv    = (const float*)d_in[4];
    const float* Wo    = (const float*)d_in[5];
    const float* bo    = (const float*)d_in[6];
    float* out = (float*)d_out;

    float *Qp, *Kp, *Vp, *Ap, *vmp; int* cp;
    cudaGetSymbolAddress((void**)&Qp, g_Q);
    cudaGetSymbolAddress((void**)&Kp, g_K);
    cudaGetSymbolAddress((void**)&Vp, g_V);
    cudaGetSymbolAddress((void**)&Ap, g_A);
    cudaGetSymbolAddress((void**)&vmp, g_vmean);
    cudaGetSymbolAddress((void**)&cp, g_code);

    code_kernel<<<16, 256>>>(gmask, cp);
    dim3 ggrid(D_MODEL / 64, N_TOK / 64);
    gemm64<<<ggrid, 256>>>(x, Wq, nullptr, Qp, N_TOK, D_MODEL, D_MODEL);
    gemm64<<<ggrid, 256>>>(x, Wk, nullptr, Kp, N_TOK, D_MODEL, D_MODEL);
    gemm64<<<ggrid, 256>>>(x, Wv, nullptr, Vp, N_TOK, D_MODEL, D_MODEL);
    vmean_kernel<<<D_MODEL, 256>>>(Vp, vmp);
    attn_kernel<<<dim3(N_TOK / 64, HEADS), 256>>>(Qp, Kp, Vp, cp, vmp, Ap);
    gemm64<<<ggrid, 256>>>(Ap, Wo, bo, out, N_TOK, D_MODEL, D_MODEL);
}

// round 2
// speedup vs baseline: 2.5418x; 2.5418x over previous
#include <cuda_runtime.h>
#include <math.h>

#define N_TOK 4096
#define D_MODEL 320
#define HEADS 8
#define DH 40
#define SCALE 0.15811388300841897f  // 40^-0.5

// ---------------- scratch (no allocs allowed) ----------------
__device__ float g_Q[N_TOK * D_MODEL];
__device__ float g_K[N_TOK * D_MODEL];
__device__ float g_V[N_TOK * D_MODEL];
__device__ float g_A[N_TOK * D_MODEL];
__device__ int   g_code[N_TOK];
__device__ float g_vmean[D_MODEL];
__device__ int   g_klist[7 * N_TOK];
__device__ int   g_kcount[7];
__device__ int   g_qlist[7 * N_TOK];
__device__ int   g_qcount[7];

// ---------------- phase-code kernel ----------------
__global__ void code_kernel(const float* __restrict__ g, int* __restrict__ code) {
    int i = blockIdx.x * 256 + threadIdx.x;
    if (i < N_TOK) {
        int c = 0;
        if (g[i]           > 0.5f) c |= 1;
        if (g[N_TOK + i]   > 0.5f) c |= 2;
        if (g[2*N_TOK + i] > 0.5f) c |= 4;
        code[i] = c;
    }
}

// ---------------- deterministic per-class list compaction ----------------
// One block per class c=1..7. Stable order via block-wide inclusive scan.
__global__ __launch_bounds__(256) void build_lists(
    const int* __restrict__ code,
    int* __restrict__ klist, int* __restrict__ kcount,
    int* __restrict__ qlist, int* __restrict__ qcount)
{
    int c = blockIdx.x + 1;
    int tid = threadIdx.x;
    __shared__ int s[256];
    __shared__ int kbase, qbase;
    if (tid == 0) { kbase = 0; qbase = 0; }
    __syncthreads();

    int loff = (c - 1) * N_TOK;
    for (int t0 = 0; t0 < N_TOK; t0 += 256) {
        int i = t0 + tid;
        int ci = code[i];
        int kp = (ci & c) ? 1 : 0;
        int qp = (ci == c) ? 1 : 0;

        // scan K-predicate
        s[tid] = kp; __syncthreads();
        #pragma unroll
        for (int o = 1; o < 256; o <<= 1) {
            int v = (tid >= o) ? s[tid - o] : 0;
            __syncthreads();
            s[tid] += v;
            __syncthreads();
        }
        int kincl = s[tid];
        int ktot  = s[255];
        int kb    = kbase;
        __syncthreads();
        if (kp) klist[loff + kb + kincl - 1] = i;

        // scan Q-predicate
        s[tid] = qp; __syncthreads();
        #pragma unroll
        for (int o = 1; o < 256; o <<= 1) {
            int v = (tid >= o) ? s[tid - o] : 0;
            __syncthreads();
            s[tid] += v;
            __syncthreads();
        }
        int qincl = s[tid];
        int qtot  = s[255];
        int qb    = qbase;
        __syncthreads();
        if (qp) qlist[loff + qb + qincl - 1] = i;

        if (tid == 0) { kbase += ktot; qbase += qtot; }
        __syncthreads();
    }
    if (tid == 0) { kcount[c - 1] = kbase; qcount[c - 1] = qbase; }
}

// ---------------- column mean of V (for fully-masked rows) ----------------
__global__ void vmean_kernel(const float* __restrict__ V, float* __restrict__ vm) {
    __shared__ float red[256];
    int c = blockIdx.x;
    float s = 0.f;
    for (int r = threadIdx.x; r < N_TOK; r += 256) s += V[r * D_MODEL + c];
    red[threadIdx.x] = s;
    __syncthreads();
    for (int o = 128; o > 0; o >>= 1) {
        if (threadIdx.x < o) red[threadIdx.x] += red[threadIdx.x + o];
        __syncthreads();
    }
    if (threadIdx.x == 0) vm[c] = red[0] * (1.f / (float)N_TOK);
}

// ---------------- fully-masked rows -> vmean ----------------
__global__ void fill_inactive(const int* __restrict__ code,
                              const float* __restrict__ vmean,
                              float* __restrict__ A) {
    int row = blockIdx.x;
    if (code[row] != 0) return;
    for (int d = threadIdx.x; d < D_MODEL; d += 64)
        A[row * D_MODEL + d] = vmean[d];
}

// ---------------- generic tiled fp32 GEMM: C[MxN] = A[MxK]*B[KxN] (+bias) ----------------
__global__ __launch_bounds__(256) void gemm64(
    const float* __restrict__ A, const float* __restrict__ B,
    const float* __restrict__ bias, float* __restrict__ C,
    int M, int N, int K)
{
    __shared__ float As[16][68];
    __shared__ float Bs[16][68];
    int tid = threadIdx.x;
    int m0 = blockIdx.y * 64;
    int n0 = blockIdx.x * 64;
    int ty = tid >> 4, tx = tid & 15;

    int lr = tid >> 2;
    int lk = (tid & 3) * 4;
    int bk = tid >> 4;
    int bc = (tid & 15) * 4;

    float acc[4][4];
    #pragma unroll
    for (int i = 0; i < 4; ++i)
        #pragma unroll
        for (int j = 0; j < 4; ++j) acc[i][j] = 0.f;

    for (int k0 = 0; k0 < K; k0 += 16) {
        float4 av = *(const float4*)&A[(m0 + lr) * K + k0 + lk];
        As[lk + 0][lr] = av.x; As[lk + 1][lr] = av.y;
        As[lk + 2][lr] = av.z; As[lk + 3][lr] = av.w;
        float4 bv = *(const float4*)&B[(k0 + bk) * N + n0 + bc];
        *(float4*)&Bs[bk][bc] = bv;
        __syncthreads();
        #pragma unroll
        for (int kk = 0; kk < 16; ++kk) {
            float a[4], b[4];
            #pragma unroll
            for (int i = 0; i < 4; ++i) a[i] = As[kk][ty * 4 + i];
            #pragma unroll
            for (int j = 0; j < 4; ++j) b[j] = Bs[kk][tx * 4 + j];
            #pragma unroll
            for (int i = 0; i < 4; ++i)
                #pragma unroll
                for (int j = 0; j < 4; ++j)
                    acc[i][j] = fmaf(a[i], b[j], acc[i][j]);
        }
        __syncthreads();
    }
    #pragma unroll
    for (int i = 0; i < 4; ++i) {
        int row = m0 + ty * 4 + i;
        #pragma unroll
        for (int j = 0; j < 4; ++j) {
            int col = n0 + tx * 4 + j;
            float v = acc[i][j];
            if (bias) v += bias[col];
            C[row * N + col] = v;
        }
    }
}

// ---------------- class-compacted flash attention ----------------
// grid (7 classes * 64 qtiles, 8 heads), 256 threads = 64 query slots x 4 lanes.
// All queries in a block share one code class; the key list for that class is
// fully attendable -> no masking, no divergence in the mainloop.
__global__ __launch_bounds__(256) void attn_kernel(
    const float* __restrict__ Q, const float* __restrict__ Km,
    const float* __restrict__ Vm,
    const int* __restrict__ klist, const int* __restrict__ kcount,
    const int* __restrict__ qlist, const int* __restrict__ qcount,
    float* __restrict__ out)
{
    int cls = blockIdx.x >> 6;
    int qt  = blockIdx.x & 63;
    int h   = blockIdx.y;
    int nQ = qcount[cls];
    if (qt * 64 >= nQ) return;
    int nK = kcount[cls];

    int tid = threadIdx.x;
    int grp = tid >> 2, lane4 = tid & 3;
    int qslot = qt * 64 + grp;
    bool valid = qslot < nQ;
    int row = valid ? qlist[cls * N_TOK + qslot] : 0;
    int hoff = h * DH;

    __shared__ float Ksm[64 * DH];
    __shared__ float Vsm[64 * DH];

    float q[DH];
    if (valid) {
        #pragma unroll
        for (int d4 = 0; d4 < 10; ++d4) {
            float4 t = *(const float4*)&Q[row * D_MODEL + hoff + d4 * 4];
            q[d4*4+0] = t.x; q[d4*4+1] = t.y; q[d4*4+2] = t.z; q[d4*4+3] = t.w;
        }
    }

    float m = -1e30f, l = 0.f;
    float O[DH];
    #pragma unroll
    for (int d = 0; d < DH; ++d) O[d] = 0.f;

    const int* kl = klist + cls * N_TOK;
    int ntiles = (nK + 63) >> 6;

    for (int kt = 0; kt < ntiles; ++kt) {
        int base = kt << 6;
        int rem = nK - base;           // >= 1
        int nloc = rem < 64 ? rem : 64;
        // gather K/V tile
        for (int v2 = tid; v2 < 640; v2 += 256) {
            int r = v2 / 10, d4 = v2 - r * 10;
            if (r < nloc) {
                int j = kl[base + r];
                int gi = j * D_MODEL + hoff + d4 * 4;
                *(float4*)&Ksm[r * DH + d4 * 4] = *(const float4*)&Km[gi];
                *(float4*)&Vsm[r * DH + d4 * 4] = *(const float4*)&Vm[gi];
            }
        }
        __syncthreads();
        if (valid) {
            #pragma unroll 2
            for (int s = 0; s < 16; ++s) {
                int jj = (s << 2) | lane4;   // interleaved: conflict-free LDS
                if (jj >= nloc) break;       // only trips in the tail tile
                const float4* kp = (const float4*)(Ksm + jj * DH);
                float d0 = 0.f, d1 = 0.f;
                #pragma unroll
                for (int d4 = 0; d4 < 10; d4 += 2) {
                    float4 k0 = kp[d4], k1 = kp[d4 + 1];
                    d0 = fmaf(q[d4*4+0], k0.x, d0); d0 = fmaf(q[d4*4+1], k0.y, d0);
                    d0 = fmaf(q[d4*4+2], k0.z, d0); d0 = fmaf(q[d4*4+3], k0.w, d0);
                    d1 = fmaf(q[d4*4+4], k1.x, d1); d1 = fmaf(q[d4*4+5], k1.y, d1);
                    d1 = fmaf(q[d4*4+6], k1.z, d1); d1 = fmaf(q[d4*4+7], k1.w, d1);
                }
                float sc = (d0 + d1) * SCALE;
                const float4* vp = (const float4*)(Vsm + jj * DH);
                if (sc <= m) {
                    float p = __expf(sc - m);
                    l += p;
                    #pragma unroll
                    for (int d4 = 0; d4 < 10; ++d4) {
                        float4 vv = vp[d4];
                        O[d4*4+0] = fmaf(p, vv.x, O[d4*4+0]);
                        O[d4*4+1] = fmaf(p, vv.y, O[d4*4+1]);
                        O[d4*4+2] = fmaf(p, vv.z, O[d4*4+2]);
                        O[d4*4+3] = fmaf(p, vv.w, O[d4*4+3]);
                    }
                } else {
                    float f = __expf(m - sc);
                    m = sc;
                    l = fmaf(l, f, 1.f);
                    #pragma unroll
                    for (int d4 = 0; d4 < 10; ++d4) {
                        float4 vv = vp[d4];
                        O[d4*4+0] = fmaf(O[d4*4+0], f, vv.x);
                        O[d4*4+1] = fmaf(O[d4*4+1], f, vv.y);
                        O[d4*4+2] = fmaf(O[d4*4+2], f, vv.z);
                        O[d4*4+3] = fmaf(O[d4*4+3], f, vv.w);
                    }
                }
            }
        }
        __syncthreads();
    }

    // merge (m,l,O) across the 4 lanes of each row group
    #pragma unroll
    for (int off = 1; off < 4; off <<= 1) {
        float mo = __shfl_xor_sync(0xffffffffu, m, off);
        float lo = __shfl_xor_sync(0xffffffffu, l, off);
        float mn = fmaxf(m, mo);
        float a = __expf(m - mn);
        float b = __expf(mo - mn);
        l = l * a + lo * b;
        #pragma unroll
        for (int d = 0; d < DH; ++d) {
            float od = __shfl_xor_sync(0xffffffffu, O[d], off);
            O[d] = O[d] * a + od * b;
        }
        m = mn;
    }

    if (valid) {
        float inv = 1.f / l;
        #pragma unroll
        for (int d = 0; d < 10; ++d)
            out[row * D_MODEL + hoff + lane4 * 10 + d] = O[lane4 * 10 + d] * inv;
    }
}

extern "C" void kernel_launch(void* const* d_in, const int* in_sizes, int n_in,
                              void* d_out, int out_size) {
    const float* x     = (const float*)d_in[0];
    const float* gmask = (const float*)d_in[1];
    const float* Wq    = (const float*)d_in[2];
    const float* Wk    = (const float*)d_in[3];
    const float* Wv    = (const float*)d_in[4];
    const float* Wo    = (const float*)d_in[5];
    const float* bo    = (const float*)d_in[6];
    float* out = (float*)d_out;

    float *Qp, *Kp, *Vp, *Ap, *vmp; int *cp, *klp, *kcp, *qlp, *qcp;
    cudaGetSymbolAddress((void**)&Qp, g_Q);
    cudaGetSymbolAddress((void**)&Kp, g_K);
    cudaGetSymbolAddress((void**)&Vp, g_V);
    cudaGetSymbolAddress((void**)&Ap, g_A);
    cudaGetSymbolAddress((void**)&vmp, g_vmean);
    cudaGetSymbolAddress((void**)&cp, g_code);
    cudaGetSymbolAddress((void**)&klp, g_klist);
    cudaGetSymbolAddress((void**)&kcp, g_kcount);
    cudaGetSymbolAddress((void**)&qlp, g_qlist);
    cudaGetSymbolAddress((void**)&qcp, g_qcount);

    code_kernel<<<16, 256>>>(gmask, cp);
    build_lists<<<7, 256>>>(cp, klp, kcp, qlp, qcp);
    dim3 ggrid(D_MODEL / 64, N_TOK / 64);
    gemm64<<<ggrid, 256>>>(x, Wq, nullptr, Qp, N_TOK, D_MODEL, D_MODEL);
    gemm64<<<ggrid, 256>>>(x, Wk, nullptr, Kp, N_TOK, D_MODEL, D_MODEL);
    gemm64<<<ggrid, 256>>>(x, Wv, nullptr, Vp, N_TOK, D_MODEL, D_MODEL);
    vmean_kernel<<<D_MODEL, 256>>>(Vp, vmp);
    attn_kernel<<<dim3(7 * 64, HEADS), 256>>>(Qp, Kp, Vp, klp, kcp, qlp, qcp, Ap);
    fill_inactive<<<N_TOK, 64>>>(cp, vmp, Ap);
    gemm64<<<ggrid, 256>>>(Ap, Wo, bo, out, N_TOK, D_MODEL, D_MODEL);
}

// round 3
// speedup vs baseline: 2.7204x; 1.0703x over previous
#include <cuda_runtime.h>
#include <math.h>

#define N_TOK 4096
#define D_MODEL 320
#define HEADS 8
#define DH 40
#define SCALE 0.15811388300841897f  // 40^-0.5
#define NEG_BIG  (-3.0e38f)
#define M_INIT   (-1.0e37f)

// ---------------- scratch (no allocs allowed) ----------------
__device__ float g_Q[N_TOK * D_MODEL];
__device__ float g_K[N_TOK * D_MODEL];
__device__ float g_V[N_TOK * D_MODEL];
__device__ float g_A[N_TOK * D_MODEL];
__device__ int   g_code[N_TOK];
__device__ float g_vmean[D_MODEL];
__device__ int   g_klist[7 * N_TOK];
__device__ int   g_kcount[7];
__device__ int   g_qlist[7 * N_TOK];
__device__ int   g_qcount[7];

// ---------------- phase-code kernel ----------------
__global__ void code_kernel(const float* __restrict__ g, int* __restrict__ code) {
    int i = blockIdx.x * 256 + threadIdx.x;
    if (i < N_TOK) {
        int c = 0;
        if (g[i]           > 0.5f) c |= 1;
        if (g[N_TOK + i]   > 0.5f) c |= 2;
        if (g[2*N_TOK + i] > 0.5f) c |= 4;
        code[i] = c;
    }
}

// ---------------- deterministic per-class list compaction (ballot scan) ----------------
__global__ __launch_bounds__(256) void build_lists(
    const int* __restrict__ code,
    int* __restrict__ klist, int* __restrict__ kcount,
    int* __restrict__ qlist, int* __restrict__ qcount)
{
    int c = blockIdx.x + 1;
    int tid = threadIdx.x;
    int lane = tid & 31, wid = tid >> 5;
    __shared__ int wk[8], wq[8];
    __shared__ int kbase, qbase;
    if (tid == 0) { kbase = 0; qbase = 0; }
    __syncthreads();

    int loff = (c - 1) * N_TOK;
    for (int t0 = 0; t0 < N_TOK; t0 += 256) {
        int i = t0 + tid;
        int ci = code[i];
        int kp = (ci & c) ? 1 : 0;
        int qp = (ci == c) ? 1 : 0;

        unsigned kb = __ballot_sync(0xffffffffu, kp);
        unsigned qb = __ballot_sync(0xffffffffu, qp);
        int kpre = __popc(kb & ((1u << lane) - 1));
        int qpre = __popc(qb & ((1u << lane) - 1));
        if (lane == 0) { wk[wid] = __popc(kb); wq[wid] = __popc(qb); }
        __syncthreads();
        if (tid == 0) {
            int rk = kbase, rq = qbase;
            #pragma unroll
            for (int w = 0; w < 8; ++w) {
                int tk = wk[w]; wk[w] = rk; rk += tk;
                int tq = wq[w]; wq[w] = rq; rq += tq;
            }
            kbase = rk; qbase = rq;
        }
        __syncthreads();
        if (kp) klist[loff + wk[wid] + kpre] = i;
        if (qp) qlist[loff + wq[wid] + qpre] = i;
        __syncthreads();
    }
    if (tid == 0) { kcount[c - 1] = kbase; qcount[c - 1] = qbase; }
}

// ---------------- column mean of V (for fully-masked rows) ----------------
__global__ void vmean_kernel(const float* __restrict__ V, float* __restrict__ vm) {
    __shared__ float red[256];
    int c = blockIdx.x;
    float s = 0.f;
    for (int r = threadIdx.x; r < N_TOK; r += 256) s += V[r * D_MODEL + c];
    red[threadIdx.x] = s;
    __syncthreads();
    for (int o = 128; o > 0; o >>= 1) {
        if (threadIdx.x < o) red[threadIdx.x] += red[threadIdx.x + o];
        __syncthreads();
    }
    if (threadIdx.x == 0) vm[c] = red[0] * (1.f / (float)N_TOK);
}

// ---------------- fully-masked rows -> vmean ----------------
__global__ void fill_inactive(const int* __restrict__ code,
                              const float* __restrict__ vmean,
                              float* __restrict__ A) {
    int row = blockIdx.x;
    if (code[row] != 0) return;
    for (int d = threadIdx.x; d < D_MODEL; d += 64)
        A[row * D_MODEL + d] = vmean[d];
}

// ---------------- tiled fp32 GEMM body ----------------
__device__ __forceinline__ void gemm64_body(
    const float* __restrict__ A, const float* __restrict__ B,
    const float* __restrict__ bias, float* __restrict__ C,
    int M, int N, int K, int m0, int n0)
{
    __shared__ float As[16][68];
    __shared__ float Bs[16][68];
    int tid = threadIdx.x;
    int ty = tid >> 4, tx = tid & 15;

    int lr = tid >> 2;
    int lk = (tid & 3) * 4;
    int bk = tid >> 4;
    int bc = (tid & 15) * 4;

    float acc[4][4];
    #pragma unroll
    for (int i = 0; i < 4; ++i)
        #pragma unroll
        for (int j = 0; j < 4; ++j) acc[i][j] = 0.f;

    for (int k0 = 0; k0 < K; k0 += 16) {
        float4 av = *(const float4*)&A[(m0 + lr) * K + k0 + lk];
        As[lk + 0][lr] = av.x; As[lk + 1][lr] = av.y;
        As[lk + 2][lr] = av.z; As[lk + 3][lr] = av.w;
        float4 bv = *(const float4*)&B[(k0 + bk) * N + n0 + bc];
        *(float4*)&Bs[bk][bc] = bv;
        __syncthreads();
        #pragma unroll
        for (int kk = 0; kk < 16; ++kk) {
            float a[4], b[4];
            #pragma unroll
            for (int i = 0; i < 4; ++i) a[i] = As[kk][ty * 4 + i];
            #pragma unroll
            for (int j = 0; j < 4; ++j) b[j] = Bs[kk][tx * 4 + j];
            #pragma unroll
            for (int i = 0; i < 4; ++i)
                #pragma unroll
                for (int j = 0; j < 4; ++j)
                    acc[i][j] = fmaf(a[i], b[j], acc[i][j]);
        }
        __syncthreads();
    }
    #pragma unroll
    for (int i = 0; i < 4; ++i) {
        int row = m0 + ty * 4 + i;
        #pragma unroll
        for (int j = 0; j < 4; ++j) {
            int col = n0 + tx * 4 + j;
            float v = acc[i][j];
            if (bias) v += bias[col];
            C[row * N + col] = v;
        }
    }
}

__global__ __launch_bounds__(256) void gemm64(
    const float* __restrict__ A, const float* __restrict__ B,
    const float* __restrict__ bias, float* __restrict__ C,
    int M, int N, int K)
{
    gemm64_body(A, B, bias, C, M, N, K, blockIdx.y * 64, blockIdx.x * 64);
}

// fused QKV: grid.z selects weight/output, all share A = x
__global__ __launch_bounds__(256) void gemm64_qkv(
    const float* __restrict__ A,
    const float* __restrict__ Wq, const float* __restrict__ Wk,
    const float* __restrict__ Wv,
    float* __restrict__ Q, float* __restrict__ K, float* __restrict__ V)
{
    const float* B = (blockIdx.z == 0) ? Wq : (blockIdx.z == 1) ? Wk : Wv;
    float* C = (blockIdx.z == 0) ? Q : (blockIdx.z == 1) ? K : V;
    gemm64_body(A, B, nullptr, C, N_TOK, D_MODEL, D_MODEL,
                blockIdx.y * 64, blockIdx.x * 64);
}

// ---------------- class-compacted branchless flash attention ----------------
// grid (7 classes * 64 qtiles, 8 heads), 256 threads = 64 query slots x 4 lanes.
// Tile-max online softmax: one rescale per 16-key lane-tile, no branches.
__global__ __launch_bounds__(256) void attn_kernel(
    const float* __restrict__ Q, const float* __restrict__ Km,
    const float* __restrict__ Vm,
    const int* __restrict__ klist, const int* __restrict__ kcount,
    const int* __restrict__ qlist, const int* __restrict__ qcount,
    float* __restrict__ out)
{
    int cls = blockIdx.x >> 6;
    int qt  = blockIdx.x & 63;
    int h   = blockIdx.y;
    int nQ = qcount[cls];
    if (qt * 64 >= nQ) return;
    int nK = kcount[cls];

    int tid = threadIdx.x;
    int grp = tid >> 2, lane4 = tid & 3;
    int qslot = qt * 64 + grp;
    bool valid = qslot < nQ;
    int row = valid ? qlist[cls * N_TOK + qslot] : qlist[cls * N_TOK];
    int hoff = h * DH;

    __shared__ float Ksm[64 * DH];
    __shared__ float Vsm[64 * DH];

    float q[DH];
    #pragma unroll
    for (int d4 = 0; d4 < 10; ++d4) {
        float4 t = *(const float4*)&Q[row * D_MODEL + hoff + d4 * 4];
        q[d4*4+0] = t.x; q[d4*4+1] = t.y; q[d4*4+2] = t.z; q[d4*4+3] = t.w;
    }

    float m = M_INIT, l = 0.f;
    float O[DH];
    #pragma unroll
    for (int d = 0; d < DH; ++d) O[d] = 0.f;

    const int* kl = klist + cls * N_TOK;
    int ntiles = (nK + 63) >> 6;

    for (int kt = 0; kt < ntiles; ++kt) {
        int base = kt << 6;
        int nloc = nK - base; if (nloc > 64) nloc = 64;
        for (int v2 = tid; v2 < 640; v2 += 256) {
            int r = v2 / 10, d4 = v2 - r * 10;
            if (r < nloc) {
                int j = kl[base + r];
                int gi = j * D_MODEL + hoff + d4 * 4;
                *(float4*)&Ksm[r * DH + d4 * 4] = *(const float4*)&Km[gi];
                *(float4*)&Vsm[r * DH + d4 * 4] = *(const float4*)&Vm[gi];
            }
        }
        __syncthreads();

        // 1) scores for this lane's 16 keys (invalid -> NEG_BIG)
        float sc[16];
        #pragma unroll
        for (int s = 0; s < 16; ++s) {
            int jj = (s << 2) | lane4;
            const float4* kp = (const float4*)(Ksm + jj * DH);
            float d0 = 0.f, d1 = 0.f;
            #pragma unroll
            for (int d4 = 0; d4 < 10; d4 += 2) {
                float4 k0 = kp[d4], k1 = kp[d4 + 1];
                d0 = fmaf(q[d4*4+0], k0.x, d0); d0 = fmaf(q[d4*4+1], k0.y, d0);
                d0 = fmaf(q[d4*4+2], k0.z, d0); d0 = fmaf(q[d4*4+3], k0.w, d0);
                d1 = fmaf(q[d4*4+4], k1.x, d1); d1 = fmaf(q[d4*4+5], k1.y, d1);
                d1 = fmaf(q[d4*4+6], k1.z, d1); d1 = fmaf(q[d4*4+7], k1.w, d1);
            }
            float v = (d0 + d1) * SCALE;
            sc[s] = (jj < nloc) ? v : NEG_BIG;
        }
        // 2) tile max, single rescale
        float tmax = sc[0];
        #pragma unroll
        for (int s = 1; s < 16; ++s) tmax = fmaxf(tmax, sc[s]);
        float mn = fmaxf(m, tmax);
        float f = __expf(m - mn);
        m = mn;
        l *= f;
        #pragma unroll
        for (int d = 0; d < DH; ++d) O[d] *= f;
        // 3) accumulate
        #pragma unroll
        for (int s = 0; s < 16; ++s) {
            int jj = (s << 2) | lane4;
            float p = __expf(sc[s] - m);   // 0 for invalid keys
            l += p;
            const float4* vp = (const float4*)(Vsm + jj * DH);
            #pragma unroll
            for (int d4 = 0; d4 < 10; ++d4) {
                float4 vv = vp[d4];
                O[d4*4+0] = fmaf(p, vv.x, O[d4*4+0]);
                O[d4*4+1] = fmaf(p, vv.y, O[d4*4+1]);
                O[d4*4+2] = fmaf(p, vv.z, O[d4*4+2]);
                O[d4*4+3] = fmaf(p, vv.w, O[d4*4+3]);
            }
        }
        __syncthreads();
    }

    // merge (m,l,O) across the 4 lanes of each row group
    #pragma unroll
    for (int off = 1; off < 4; off <<= 1) {
        float mo = __shfl_xor_sync(0xffffffffu, m, off);
        float lo = __shfl_xor_sync(0xffffffffu, l, off);
        float mn = fmaxf(m, mo);
        float a = __expf(m - mn);
        float b = __expf(mo - mn);
        l = l * a + lo * b;
        #pragma unroll
        for (int d = 0; d < DH; ++d) {
            float od = __shfl_xor_sync(0xffffffffu, O[d], off);
            O[d] = O[d] * a + od * b;
        }
        m = mn;
    }

    if (valid) {
        float inv = 1.f / l;
        #pragma unroll
        for (int d = 0; d < 10; ++d)
            out[row * D_MODEL + hoff + lane4 * 10 + d] = O[lane4 * 10 + d] * inv;
    }
}

extern "C" void kernel_launch(void* const* d_in, const int* in_sizes, int n_in,
                              void* d_out, int out_size) {
    const float* x     = (const float*)d_in[0];
    const float* gmask = (const float*)d_in[1];
    const float* Wq    = (const float*)d_in[2];
    const float* Wk    = (const float*)d_in[3];
    const float* Wv    = (const float*)d_in[4];
    const float* Wo    = (const float*)d_in[5];
    const float* bo    = (const float*)d_in[6];
    float* out = (float*)d_out;

    float *Qp, *Kp, *Vp, *Ap, *vmp; int *cp, *klp, *kcp, *qlp, *qcp;
    cudaGetSymbolAddress((void**)&Qp, g_Q);
    cudaGetSymbolAddress((void**)&Kp, g_K);
    cudaGetSymbolAddress((void**)&Vp, g_V);
    cudaGetSymbolAddress((void**)&Ap, g_A);
    cudaGetSymbolAddress((void**)&vmp, g_vmean);
    cudaGetSymbolAddress((void**)&cp, g_code);
    cudaGetSymbolAddress((void**)&klp, g_klist);
    cudaGetSymbolAddress((void**)&kcp, g_kcount);
    cudaGetSymbolAddress((void**)&qlp, g_qlist);
    cudaGetSymbolAddress((void**)&qcp, g_qcount);

    code_kernel<<<16, 256>>>(gmask, cp);
    build_lists<<<7, 256>>>(cp, klp, kcp, qlp, qcp);
    gemm64_qkv<<<dim3(D_MODEL / 64, N_TOK / 64, 3), 256>>>(x, Wq, Wk, Wv, Qp, Kp, Vp);
    vmean_kernel<<<D_MODEL, 256>>>(Vp, vmp);
    attn_kernel<<<dim3(7 * 64, HEADS), 256>>>(Qp, Kp, Vp, klp, kcp, qlp, qcp, Ap);
    fill_inactive<<<N_TOK, 64>>>(cp, vmp, Ap);
    gemm64<<<dim3(D_MODEL / 64, N_TOK / 64), 256>>>(Ap, Wo, bo, out, N_TOK, D_MODEL, D_MODEL);
}